// round 10
// baseline (speedup 1.0000x reference)
#include <cuda_runtime.h>
#include <math.h>
#include <stdint.h>

// Problem constants
#define NTOK 32768      // 8 * 4096 tokens
#define DIN  1536       // D + DC
#define DH   3072       // 2 * din
#define NE   64         // experts
#define DI   1024       // D
#define DCND 512        // DC

// GEMM1 tiling: CTA 128 tokens x 128 hcols, K-chunk 32
#define KC     32
#define NCHUNK (DIN / KC)        // 48
// Fragment-major smem (floats). A: 32 blocks (R*4+S) x (32 lanes * 4 + 4 skew)=132.
// B: 64 blocks (CB*4+S) x 132, per-lane float4 = [bhi_k0, bhi_k4, blo_k0, blo_k4].
#define A_HI   0
#define A_LO   4224              // 32*132
#define B_IL   8448
#define STG_F  16896             // floats per stage (67584 B)
#define SMEM1_BYTES (2 * STG_F * 4)   // 135168 B

// Scratch for h = gelu(X @ W1^T): 32768 x 3072 fp32 = 402 MB
static __device__ float g_h[(size_t)NTOK * DH];

__device__ __forceinline__ float gelu_exact(float x) {
    return 0.5f * x * (1.0f + erff(x * 0.7071067811865475f));
}

// Round to tf32 (RNA), hi + tf32-rounded residual lo.
__device__ __forceinline__ void tf32_split(float x, float& h, float& l) {
    uint32_t t;
    asm("cvt.rna.tf32.f32 %0, %1;" : "=r"(t) : "f"(x));
    h = __uint_as_float(t);
    float r = x - h;
    asm("cvt.rna.tf32.f32 %0, %1;" : "=r"(t) : "f"(r));
    l = __uint_as_float(t);
}

__device__ __forceinline__ void mma1688(float c[4], const uint32_t a[4],
                                        uint32_t b0, uint32_t b1) {
    asm volatile(
        "mma.sync.aligned.m16n8k8.row.col.f32.tf32.tf32.f32 "
        "{%0,%1,%2,%3}, {%4,%5,%6,%7}, {%8,%9}, {%0,%1,%2,%3};"
        : "+f"(c[0]), "+f"(c[1]), "+f"(c[2]), "+f"(c[3])
        : "r"(a[0]), "r"(a[1]), "r"(a[2]), "r"(a[3]), "r"(b0), "r"(b1));
}

__device__ __forceinline__ void load_chunk_g1(
    int c, int tid, int nblk, int mblk,
    const float* __restrict__ inp, const float* __restrict__ cnd,
    const float* __restrict__ W1, float4 pa[4], float4 pb[4])
{
    const int kbase = c * KC;
#pragma unroll
    for (int it = 0; it < 4; ++it) {
        const int idx = tid + it * 256;
        const int row = idx >> 3, c4 = idx & 7;
        const int kk = kbase + c4 * 4;
        const float* asrc = (kk < DI)
            ? inp + (size_t)(nblk + row) * DI   + kk
            : cnd + (size_t)(nblk + row) * DCND + (kk - DI);
        pa[it] = *(const float4*)asrc;
        pb[it] = *(const float4*)(W1 + (size_t)(mblk + row) * DIN + kk);
    }
}

__device__ __forceinline__ void store_chunk_g1(
    float* __restrict__ st, int tid, const float4 pa[4], const float4 pb[4])
{
#pragma unroll
    for (int it = 0; it < 4; ++it) {
        const int idx = tid + it * 256;
        const int row = idx >> 3, c4 = idx & 7;
        const int S  = c4 >> 1;        // k-step (k8 index)
        const int kq = c4 & 1;         // k>=4 within k8
        // ---- A: element (row, k) -> lane=(row&7)*4+j, q=(row&15>=8)+2*kq
        {
            const int R  = row >> 4;
            const int hb = (row >> 3) & 1;
            const int base = (R * 4 + S) * 132 + (row & 7) * 16 + hb + 2 * kq;
            float4 h, l;
            tf32_split(pa[it].x, h.x, l.x); tf32_split(pa[it].y, h.y, l.y);
            tf32_split(pa[it].z, h.z, l.z); tf32_split(pa[it].w, h.w, l.w);
            st[A_HI + base +  0] = h.x; st[A_HI + base +  4] = h.y;
            st[A_HI + base +  8] = h.z; st[A_HI + base + 12] = h.w;
            st[A_LO + base +  0] = l.x; st[A_LO + base +  4] = l.y;
            st[A_LO + base +  8] = l.z; st[A_LO + base + 12] = l.w;
        }
        // ---- B: element (k, n=row) -> lane=(row&7)*4+j, quad=[hi kq, lo kq]
        {
            const int CB = row >> 3;
            const int base = (CB * 4 + S) * 132 + (row & 7) * 16 + kq;
            float4 h, l;
            tf32_split(pb[it].x, h.x, l.x); tf32_split(pb[it].y, h.y, l.y);
            tf32_split(pb[it].z, h.z, l.z); tf32_split(pb[it].w, h.w, l.w);
            st[B_IL + base +  0] = h.x; st[B_IL + base +  4] = h.y;
            st[B_IL + base +  8] = h.z; st[B_IL + base + 12] = h.w;
            st[B_IL + base + 2 +  0] = l.x; st[B_IL + base + 2 +  4] = l.y;
            st[B_IL + base + 2 +  8] = l.z; st[B_IL + base + 2 + 12] = l.w;
        }
    }
}

// ---------------------------------------------------------------------------
// GEMM1 (mma.sync tf32, 3xTF32 split): g_h[n,m] = gelu( X[n,:] . W1[m,:] )
// ---------------------------------------------------------------------------
extern "C" __global__ void __launch_bounds__(256, 1)
k_gemm1_mma(const float* __restrict__ inp,
            const float* __restrict__ cnd,
            const float* __restrict__ W1)
{
    extern __shared__ float sm[];

    const int tid  = threadIdx.x;
    const int lane = tid & 31;
    const int wid  = tid >> 5;
    const int wm   = wid & 1;          // 0..1 : 64-token half
    const int wn   = wid >> 1;         // 0..3 : 32-hcol slice
    const int gID  = lane >> 2;        // 0..7
    const int tig  = lane & 3;         // 0..3
    const int mblk = blockIdx.x * 128; // hcol base
    const int nblk = blockIdx.y * 128; // token base

    float acc[4][4][4];
#pragma unroll
    for (int mt = 0; mt < 4; mt++)
#pragma unroll
        for (int nt = 0; nt < 4; nt++)
#pragma unroll
            for (int q = 0; q < 4; q++) acc[mt][nt][q] = 0.f;

    float4 pa[4], pb[4];

    // prologue: chunk 0 into regs
    load_chunk_g1(0, tid, nblk, mblk, inp, cnd, W1, pa, pb);

    for (int c = 0; c < NCHUNK; ++c) {
        const int buf = c & 1;
        store_chunk_g1(sm + buf * STG_F, tid, pa, pb);     // overlaps laggards' compute(c-1)
        if (c + 1 < NCHUNK)
            load_chunk_g1(c + 1, tid, nblk, mblk, inp, cnd, W1, pa, pb);
        __syncthreads();                                    // stage[buf] visible to all

        const float* st = sm + buf * STG_F;
#pragma unroll
        for (int ks = 0; ks < 4; ++ks) {
            uint32_t ahi[4][4], alo[4][4], bb[4][4];
#pragma unroll
            for (int mt = 0; mt < 4; ++mt) {
                const int off = ((wm * 4 + mt) * 4 + ks) * 132 + lane * 4;
                float4 vh = *(const float4*)(st + A_HI + off);
                float4 vl = *(const float4*)(st + A_LO + off);
                ahi[mt][0] = __float_as_uint(vh.x); ahi[mt][1] = __float_as_uint(vh.y);
                ahi[mt][2] = __float_as_uint(vh.z); ahi[mt][3] = __float_as_uint(vh.w);
                alo[mt][0] = __float_as_uint(vl.x); alo[mt][1] = __float_as_uint(vl.y);
                alo[mt][2] = __float_as_uint(vl.z); alo[mt][3] = __float_as_uint(vl.w);
            }
#pragma unroll
            for (int nt = 0; nt < 4; ++nt) {
                const int off = ((wn * 4 + nt) * 4 + ks) * 132 + lane * 4;
                float4 v = *(const float4*)(st + B_IL + off);
                bb[nt][0] = __float_as_uint(v.x); bb[nt][1] = __float_as_uint(v.y);
                bb[nt][2] = __float_as_uint(v.z); bb[nt][3] = __float_as_uint(v.w);
            }
            // pass-major: 16 independent accs between reuses (no RAW stalls)
#pragma unroll
            for (int mt = 0; mt < 4; ++mt)
#pragma unroll
                for (int nt = 0; nt < 4; ++nt)
                    mma1688(acc[mt][nt], ahi[mt], bb[nt][0], bb[nt][1]);   // hi*hi
#pragma unroll
            for (int mt = 0; mt < 4; ++mt)
#pragma unroll
                for (int nt = 0; nt < 4; ++nt)
                    mma1688(acc[mt][nt], ahi[mt], bb[nt][2], bb[nt][3]);   // hi*lo
#pragma unroll
            for (int mt = 0; mt < 4; ++mt)
#pragma unroll
                for (int nt = 0; nt < 4; ++nt)
                    mma1688(acc[mt][nt], alo[mt], bb[nt][0], bb[nt][1]);   // lo*hi
        }
    }

    // ---- epilogue: GELU + store to g_h ----
#pragma unroll
    for (int mt = 0; mt < 4; ++mt) {
        const int row0 = nblk + wm * 64 + mt * 16 + gID;
#pragma unroll
        for (int nt = 0; nt < 4; ++nt) {
            const int col = mblk + wn * 32 + nt * 8 + tig * 2;
            float2 v0, v1;
            v0.x = gelu_exact(acc[mt][nt][0]);
            v0.y = gelu_exact(acc[mt][nt][1]);
            v1.x = gelu_exact(acc[mt][nt][2]);
            v1.y = gelu_exact(acc[mt][nt][3]);
            *(float2*)(g_h + (size_t)row0 * DH + col)       = v0;
            *(float2*)(g_h + (size_t)(row0 + 8) * DH + col) = v1;
        }
    }
}

// ---------------------------------------------------------------------------
// Kernel 2 (unchanged, passing): logits + softmax + top-2 + outputs
// ---------------------------------------------------------------------------
__global__ __launch_bounds__(256, 2)
void k_gemm2(const float* __restrict__ W2, float* __restrict__ out)
{
    __shared__ float As[2][8][132];
    __shared__ float Bs[2][8][68];
    __shared__ float lg[128][65];

    const int nblk = blockIdx.x * 128;
    const int tid  = threadIdx.x;
    const int tx   = tid & 15;
    const int ty   = tid >> 4;
    const int lrow = tid >> 1;
    const int lk4  = (tid & 1) << 2;

    float acc[8][4];
#pragma unroll
    for (int i = 0; i < 8; i++)
#pragma unroll
        for (int j = 0; j < 4; j++) acc[i][j] = 0.f;

    const size_t arow = (size_t)(nblk + lrow) * DH;
    const int    erow = tid >> 1;
    const size_t brow = (size_t)erow * DH;

    float4 av, bv;
    av = *(const float4*)(g_h + arow + lk4);
    if (tid < 128) bv = *(const float4*)(W2 + brow + lk4);
    As[0][lk4+0][lrow] = av.x; As[0][lk4+1][lrow] = av.y;
    As[0][lk4+2][lrow] = av.z; As[0][lk4+3][lrow] = av.w;
    if (tid < 128) {
        Bs[0][lk4+0][erow] = bv.x; Bs[0][lk4+1][erow] = bv.y;
        Bs[0][lk4+2][erow] = bv.z; Bs[0][lk4+3][erow] = bv.w;
    }
    __syncthreads();

    int buf = 0;
    for (int k0 = 8; k0 <= DH; k0 += 8) {
        if (k0 < DH) {
            av = *(const float4*)(g_h + arow + k0 + lk4);
            if (tid < 128) bv = *(const float4*)(W2 + brow + k0 + lk4);
        }
#pragma unroll
        for (int k = 0; k < 8; k++) {
            float4 a0 = *(const float4*)&As[buf][k][ty*8];
            float4 a1 = *(const float4*)&As[buf][k][ty*8+4];
            float4 b0 = *(const float4*)&Bs[buf][k][tx*4];
            float a[8] = {a0.x,a0.y,a0.z,a0.w,a1.x,a1.y,a1.z,a1.w};
            float b[4] = {b0.x,b0.y,b0.z,b0.w};
#pragma unroll
            for (int i = 0; i < 8; i++)
#pragma unroll
                for (int j = 0; j < 4; j++)
                    acc[i][j] = fmaf(a[i], b[j], acc[i][j]);
        }
        if (k0 < DH) {
            const int nb = buf ^ 1;
            As[nb][lk4+0][lrow] = av.x; As[nb][lk4+1][lrow] = av.y;
            As[nb][lk4+2][lrow] = av.z; As[nb][lk4+3][lrow] = av.w;
            if (tid < 128) {
                Bs[nb][lk4+0][erow] = bv.x; Bs[nb][lk4+1][erow] = bv.y;
                Bs[nb][lk4+2][erow] = bv.z; Bs[nb][lk4+3][erow] = bv.w;
            }
            buf = nb;
        }
        __syncthreads();
    }

#pragma unroll
    for (int i = 0; i < 8; i++)
#pragma unroll
        for (int j = 0; j < 4; j++)
            lg[ty*8+i][tx*4+j] = acc[i][j];
    __syncthreads();

    if (tid < 128) {
        const int r = tid;
        const int n = nblk + r;

        float m1 = -1e30f; int i1 = 0;
#pragma unroll
        for (int e = 0; e < NE; e++) {
            float v = lg[r][e];
            if (v > m1) { m1 = v; i1 = e; }
        }
        float m2 = -1e30f; int i2 = 0;
#pragma unroll
        for (int e = 0; e < NE; e++) {
            if (e == i1) continue;
            float v = lg[r][e];
            if (v > m2) { m2 = v; i2 = e; }
        }
        float s = 0.f;
#pragma unroll
        for (int e = 0; e < NE; e++) s += expf(lg[r][e] - m1);
        const float inv = 1.0f / s;

        const float lo = 1e-9f, hi = 1.0f - 1e-9f;
        const float p1 = fminf(fmaxf(inv + lo, lo), hi);
        const float p2 = fminf(fmaxf(expf(m2 - m1) * inv + lo, lo), hi);
        const float rn = 1.0f / (p1 + p2);

        float* mask = out;
        float* ti   = out + (size_t)NTOK * NE;
        float* rp   = out + (size_t)NTOK * NE + (size_t)NTOK * 2;
        float* pr   = rp  + (size_t)NTOK * NE;

#pragma unroll
        for (int e = 0; e < NE; e++) {
            float v = expf(lg[r][e] - m1) * inv + lo;
            v = fminf(fmaxf(v, lo), hi);
            pr[(size_t)n * NE + e]   = v;
            mask[(size_t)n * NE + e] = (e == i1 || e == i2) ? 1.0f : 0.0f;
            rp[(size_t)n * NE + e]   = (e == i1) ? p1 * rn
                                     : (e == i2) ? p2 * rn : 0.0f;
        }
        ti[(size_t)n * 2 + 0] = (float)i1;
        ti[(size_t)n * 2 + 1] = (float)i2;
    }
}

// ---------------------------------------------------------------------------
extern "C" void kernel_launch(void* const* d_in, const int* in_sizes, int n_in,
                              void* d_out, int out_size)
{
    const float* inp = (const float*)d_in[0];   // [8,4096,1024]
    const float* cnd = (const float*)d_in[1];   // [8,4096,512]
    const float* W1  = (const float*)d_in[2];   // [3072,1536]
    const float* W2  = (const float*)d_in[3];   // [64,3072]
    float* out = (float*)d_out;

    cudaFuncSetAttribute(k_gemm1_mma, cudaFuncAttributeMaxDynamicSharedMemorySize, SMEM1_BYTES);

    dim3 g1(DH / 128, NTOK / 128);   // 24 x 256 CTAs
    k_gemm1_mma<<<g1, 256, SMEM1_BYTES>>>(inp, cnd, W1);
    k_gemm2<<<NTOK / 128, 256>>>(W2, out);
}